// round 4
// baseline (speedup 1.0000x reference)
#include <cuda_runtime.h>
#include <cstdint>

// Problem constants: B=131072, T=40, H=40, C=4
#define TT   40
#define HH   40
#define UPT  5            // hidden units per lane (8 subs cover H=40)
#define NSEQ 4            // sequences per lane (register reuse factor for weights)
#define SEQ_PER_WARP 16   // 4 groups * NSEQ
#define SEQ_PER_CTA  64   // 4 warps

typedef unsigned long long ull;

// ---- packed fp32x2 helpers (sm_103a: FFMA2 only via PTX) ----
__device__ __forceinline__ ull ffma2(ull a, ull b, ull c) {
    ull d;
    asm("fma.rn.f32x2 %0, %1, %2, %3;" : "=l"(d) : "l"(a), "l"(b), "l"(c));
    return d;
}
__device__ __forceinline__ ull pack2(float lo, float hi) {
    ull r;
    asm("mov.b64 %0, {%1, %2};" : "=l"(r) : "f"(lo), "f"(hi));
    return r;
}
__device__ __forceinline__ void unpack2(ull v, float& lo, float& hi) {
    asm("mov.b64 {%0, %1}, %2;" : "=f"(lo), "=f"(hi) : "l"(v));
}
__device__ __forceinline__ ull pack_bits(float lo, float hi) {
    return (ull)__float_as_uint(lo) | ((ull)__float_as_uint(hi) << 32);
}

// ---- fast-accurate activations (~1e-7 rel err; MUFU.TANH too coarse for argmax) ----
__device__ __forceinline__ float ex2f(float x) {
    float r; asm("ex2.approx.f32 %0, %1;" : "=f"(r) : "f"(x)); return r;
}
__device__ __forceinline__ float rcpf(float x) {
    float r; asm("rcp.approx.f32 %0, %1;" : "=f"(r) : "f"(x)); return r;
}
__device__ __forceinline__ float sigf(float x) {
    return rcpf(1.0f + ex2f(x * -1.4426950408889634f));
}
__device__ __forceinline__ float tanhfast(float x) {
    return fmaf(-2.0f, rcpf(1.0f + ex2f(x * 2.8853900817779268f)), 1.0f);
}

// Weight row per (sub, k): 12 ull slots (96B, keeps 16B alignment per row),
// slots [0..4] = (i,f) pairs, [5..9] = (g,o) pairs -> exactly 5 LDS.128 per row.
// Per-sub stride 482 ull: +2 (16B) stagger so the 8 subs' rows land on
// distinct 16B bank groups (3856 % 128 = 16) -> conflict-free wavefronts.
#define WROW 12
#define SUBSTRIDE 482

__global__ __launch_bounds__(128, 3)
void lstm_fused_kernel(const float* __restrict__ x,
                       const float* __restrict__ W_ih,
                       const float* __restrict__ W_hh,
                       const float* __restrict__ b_ih,
                       const float* __restrict__ b_hh,
                       const float* __restrict__ W_fc,
                       const float* __restrict__ b_fc,
                       float* __restrict__ out,
                       int B, int out_size)
{
    __shared__ __align__(16) ull sW[8 * SUBSTRIDE];           // 30.8 KB
    __shared__ __align__(16) ull sBif[HH], sBgo[HH], sWinIf[HH], sWinGo[HH];
    __shared__ float sWfc[4 * HH];
    __shared__ float sbfc[4];
    __shared__ float sx[SEQ_PER_CTA * (TT + 1)];              // padded rows

    const int tid = threadIdx.x;
    const int seq_base = blockIdx.x * SEQ_PER_CTA;

    // ---- fill packed weights ----
    for (int idx = tid; idx < HH * HH; idx += blockDim.x) {
        int k = idx / HH, u = idx % HH;
        int sub = u / UPT, j = u % UPT;
        ull* row = &sW[sub * SUBSTRIDE + k * WROW];
        row[j]     = pack_bits(W_hh[u * HH + k],          W_hh[(HH + u) * HH + k]);
        row[5 + j] = pack_bits(W_hh[(2*HH + u) * HH + k], W_hh[(3*HH + u) * HH + k]);
    }
    for (int u = tid; u < HH; u += blockDim.x) {
        sBif[u]   = pack_bits(b_ih[u]        + b_hh[u],        b_ih[HH + u]   + b_hh[HH + u]);
        sBgo[u]   = pack_bits(b_ih[2*HH + u] + b_hh[2*HH + u], b_ih[3*HH + u] + b_hh[3*HH + u]);
        sWinIf[u] = pack_bits(W_ih[u],        W_ih[HH + u]);
        sWinGo[u] = pack_bits(W_ih[2*HH + u], W_ih[3*HH + u]);
    }
    for (int i = tid; i < 4 * HH; i += blockDim.x) sWfc[i] = W_fc[i];
    if (tid < 4) sbfc[tid] = b_fc[tid];

    // ---- stage x (coalesced) ----
    for (int idx = tid; idx < SEQ_PER_CTA * TT; idx += blockDim.x) {
        int sq = idx / TT, t = idx % TT;
        int gb = seq_base + sq;
        sx[sq * (TT + 1) + t] = (gb < B) ? x[(size_t)gb * TT + t] : 0.0f;
    }
    __syncthreads();

    const int lane = tid & 31;
    const int w    = tid >> 5;
    const int sub  = lane & 7;          // unit slice: [sub*5, sub*5+5)
    const int grp  = lane >> 3;         // sequence group within warp
    const int u0   = sub * UPT;
    const int sq0  = w * SEQ_PER_WARP + grp * NSEQ;

    const char* __restrict__ wbase = (const char*)&sW[sub * SUBSTRIDE];
    const float* __restrict__ sx0  = &sx[sq0 * (TT + 1)];

    float h[NSEQ][UPT], c[NSEQ][UPT];
#pragma unroll
    for (int s = 0; s < NSEQ; s++)
#pragma unroll
        for (int j = 0; j < UPT; j++) { h[s][j] = 0.0f; c[s][j] = 0.0f; }

    for (int t = 0; t < TT; t++) {
        ull aif[NSEQ][UPT], ago[NSEQ][UPT];
#pragma unroll
        for (int s = 0; s < NSEQ; s++) {
            const float xv = sx0[s * (TT + 1) + t];
            const ull xt2 = pack2(xv, xv);
#pragma unroll
            for (int j = 0; j < UPT; j++) {
                aif[s][j] = ffma2(xt2, sWinIf[u0 + j], sBif[u0 + j]);
                ago[s][j] = ffma2(xt2, sWinGo[u0 + j], sBgo[u0 + j]);
            }
        }

        // k-loop: owner lane m holds units {m*5..m*5+4}; inline width-8 shuffles,
        // full unroll lets ptxas hoist SHFLs under the FMA stream.
#pragma unroll
        for (int m = 0; m < 8; m++) {
            const char* base = wbase + (size_t)m * (UPT * WROW * 8);
#pragma unroll
            for (int kk = 0; kk < UPT; kk++) {
                const char* row = base + kk * (WROW * 8);
                const ulonglong2 w01 = *reinterpret_cast<const ulonglong2*>(row);
                const ulonglong2 w23 = *reinterpret_cast<const ulonglong2*>(row + 16);
                const ulonglong2 wg0 = *reinterpret_cast<const ulonglong2*>(row + 32); // w4, g0
                const ulonglong2 g12 = *reinterpret_cast<const ulonglong2*>(row + 48);
                const ulonglong2 g34 = *reinterpret_cast<const ulonglong2*>(row + 64);
#pragma unroll
                for (int s = 0; s < NSEQ; s++) {
                    const float hk = __shfl_sync(0xffffffffu, h[s][kk], m, 8);
                    const ull hk2 = pack2(hk, hk);
                    aif[s][0] = ffma2(hk2, w01.x, aif[s][0]);
                    aif[s][1] = ffma2(hk2, w01.y, aif[s][1]);
                    aif[s][2] = ffma2(hk2, w23.x, aif[s][2]);
                    aif[s][3] = ffma2(hk2, w23.y, aif[s][3]);
                    aif[s][4] = ffma2(hk2, wg0.x, aif[s][4]);
                    ago[s][0] = ffma2(hk2, wg0.y, ago[s][0]);
                    ago[s][1] = ffma2(hk2, g12.x, ago[s][1]);
                    ago[s][2] = ffma2(hk2, g12.y, ago[s][2]);
                    ago[s][3] = ffma2(hk2, g34.x, ago[s][3]);
                    ago[s][4] = ffma2(hk2, g34.y, ago[s][4]);
                }
            }
        }

        // activations + state update
#pragma unroll
        for (int s = 0; s < NSEQ; s++) {
#pragma unroll
            for (int j = 0; j < UPT; j++) {
                float ig, fg, gg, og;
                unpack2(aif[s][j], ig, fg);
                unpack2(ago[s][j], gg, og);
                const float iv = sigf(ig);
                const float fv = sigf(fg);
                const float gv = tanhfast(gg);
                const float ov = sigf(og);
                // mirror jax rounding: c_new = rn(rn(f*c) + rn(i*g))
                const float cn = __fadd_rn(__fmul_rn(fv, c[s][j]), __fmul_rn(iv, gv));
                c[s][j] = cn;
                h[s][j] = __fmul_rn(ov, tanhfast(cn));
            }
        }
        // warp-synchronous: next step's shuffles (full-mask) see updated h
    }

    // ---- FC head: per-lane partials, xor-reduce over the 8-lane sub group ----
    float lg[NSEQ][4];
#pragma unroll
    for (int s = 0; s < NSEQ; s++) {
#pragma unroll
        for (int cc = 0; cc < 4; cc++) {
            float p = 0.0f;
#pragma unroll
            for (int j = 0; j < UPT; j++) p = fmaf(h[s][j], sWfc[cc * HH + u0 + j], p);
            p += __shfl_xor_sync(0xffffffffu, p, 1, 8);
            p += __shfl_xor_sync(0xffffffffu, p, 2, 8);
            p += __shfl_xor_sync(0xffffffffu, p, 4, 8);
            lg[s][cc] = __fadd_rn(p, sbfc[cc]);
        }
    }

    if (sub == 0) {
#pragma unroll
        for (int s = 0; s < NSEQ; s++) {
            const int b = seq_base + sq0 + s;
            if (b < B) {
                reinterpret_cast<float4*>(out)[b] =
                    make_float4(lg[s][0], lg[s][1], lg[s][2], lg[s][3]);
                if (out_size >= 5 * B) {
                    float best = lg[s][0];
                    int   bi   = 0;
#pragma unroll
                    for (int cc = 1; cc < 4; cc++) {
                        if (lg[s][cc] > best) { best = lg[s][cc]; bi = cc; }
                    }
                    out[(size_t)4 * B + b] = (float)bi;
                }
            }
        }
    }
}

extern "C" void kernel_launch(void* const* d_in, const int* in_sizes, int n_in,
                              void* d_out, int out_size)
{
    const float* x    = (const float*)d_in[0];
    const float* W_ih = (const float*)d_in[1];
    const float* W_hh = (const float*)d_in[2];
    const float* b_ih = (const float*)d_in[3];
    const float* b_hh = (const float*)d_in[4];
    const float* W_fc = (const float*)d_in[5];
    const float* b_fc = (const float*)d_in[6];

    const int B = in_sizes[0] / TT;
    const int threads = 128;
    const int blocks  = (B + SEQ_PER_CTA - 1) / SEQ_PER_CTA;

    lstm_fused_kernel<<<blocks, threads>>>(x, W_ih, W_hh, b_ih, b_hh,
                                           W_fc, b_fc, (float*)d_out, B, out_size);
}

// round 5
// speedup vs baseline: 1.2464x; 1.2464x over previous
#include <cuda_runtime.h>
#include <cstdint>

// Problem constants: B=131072, T=40, H=40, C=4
#define TT   40
#define HH   40
#define UPT  5            // hidden units per lane (8 subs cover H=40)
#define NSEQ 4            // sequences per lane (register reuse factor for weights)
#define SEQ_PER_WARP 16   // 4 groups * NSEQ
#define SEQ_PER_CTA  64   // 4 warps

typedef unsigned long long ull;

// ---- packed fp32x2 helpers (sm_103a: FFMA2 only via PTX) ----
__device__ __forceinline__ ull ffma2(ull a, ull b, ull c) {
    ull d;
    asm("fma.rn.f32x2 %0, %1, %2, %3;" : "=l"(d) : "l"(a), "l"(b), "l"(c));
    return d;
}
__device__ __forceinline__ ull pack2(float lo, float hi) {
    ull r;
    asm("mov.b64 %0, {%1, %2};" : "=l"(r) : "f"(lo), "f"(hi));
    return r;
}
__device__ __forceinline__ void unpack2(ull v, float& lo, float& hi) {
    asm("mov.b64 {%0, %1}, %2;" : "=f"(lo), "=f"(hi) : "l"(v));
}
__device__ __forceinline__ ull pack_bits(float lo, float hi) {
    return (ull)__float_as_uint(lo) | ((ull)__float_as_uint(hi) << 32);
}

// ---- fast-accurate activations (~1e-7 rel err; MUFU.TANH too coarse for argmax) ----
__device__ __forceinline__ float ex2f(float x) {
    float r; asm("ex2.approx.f32 %0, %1;" : "=f"(r) : "f"(x)); return r;
}
__device__ __forceinline__ float rcpf(float x) {
    float r; asm("rcp.approx.f32 %0, %1;" : "=f"(r) : "f"(x)); return r;
}
__device__ __forceinline__ float sigf(float x) {
    return rcpf(1.0f + ex2f(x * -1.4426950408889634f));
}
__device__ __forceinline__ float tanhfast(float x) {
    return fmaf(-2.0f, rcpf(1.0f + ex2f(x * 2.8853900817779268f)), 1.0f);
}

// Weight row per (sub, k): 12 ull slots (96B, keeps 16B row alignment),
// slots [0..4] = (i,f) pairs, [5..9] = (g,o) pairs -> exactly 5 LDS.128 per row.
// Per-sub stride 482 ull: +2 (16B) stagger so the 8 subs' rows land on
// distinct 16B bank groups (3856 % 128 = 16) -> conflict-free wavefronts.
#define WROW 12
#define SUBSTRIDE 482

__global__ __launch_bounds__(128)
void lstm_fused_kernel(const float* __restrict__ x,
                       const float* __restrict__ W_ih,
                       const float* __restrict__ W_hh,
                       const float* __restrict__ b_ih,
                       const float* __restrict__ b_hh,
                       const float* __restrict__ W_fc,
                       const float* __restrict__ b_fc,
                       float* __restrict__ out,
                       int B, int out_size)
{
    __shared__ __align__(16) ull sW[8 * SUBSTRIDE];           // 30.8 KB
    __shared__ __align__(16) ull sBif[HH], sBgo[HH], sWinIf[HH], sWinGo[HH];
    __shared__ float sWfc[4 * HH];
    __shared__ float sbfc[4];
    __shared__ float sx[SEQ_PER_CTA * (TT + 1)];              // padded rows

    const int tid = threadIdx.x;
    const int seq_base = blockIdx.x * SEQ_PER_CTA;

    // ---- fill packed weights ----
    for (int idx = tid; idx < HH * HH; idx += blockDim.x) {
        int k = idx / HH, u = idx % HH;
        int sub = u / UPT, j = u % UPT;
        ull* row = &sW[sub * SUBSTRIDE + k * WROW];
        row[j]     = pack_bits(W_hh[u * HH + k],          W_hh[(HH + u) * HH + k]);
        row[5 + j] = pack_bits(W_hh[(2*HH + u) * HH + k], W_hh[(3*HH + u) * HH + k]);
    }
    for (int u = tid; u < HH; u += blockDim.x) {
        sBif[u]   = pack_bits(b_ih[u]        + b_hh[u],        b_ih[HH + u]   + b_hh[HH + u]);
        sBgo[u]   = pack_bits(b_ih[2*HH + u] + b_hh[2*HH + u], b_ih[3*HH + u] + b_hh[3*HH + u]);
        sWinIf[u] = pack_bits(W_ih[u],        W_ih[HH + u]);
        sWinGo[u] = pack_bits(W_ih[2*HH + u], W_ih[3*HH + u]);
    }
    for (int i = tid; i < 4 * HH; i += blockDim.x) sWfc[i] = W_fc[i];
    if (tid < 4) sbfc[tid] = b_fc[tid];

    // ---- stage x (coalesced) ----
    for (int idx = tid; idx < SEQ_PER_CTA * TT; idx += blockDim.x) {
        int sq = idx / TT, t = idx % TT;
        int gb = seq_base + sq;
        sx[sq * (TT + 1) + t] = (gb < B) ? x[(size_t)gb * TT + t] : 0.0f;
    }
    __syncthreads();

    const int lane = tid & 31;
    const int w    = tid >> 5;
    const int sub  = lane & 7;          // unit slice: [sub*5, sub*5+5)
    const int grp  = lane >> 3;         // sequence group within warp
    const int u0   = sub * UPT;
    const int sq0  = w * SEQ_PER_WARP + grp * NSEQ;

    const char* __restrict__ wbase = (const char*)&sW[sub * SUBSTRIDE];
    const float* __restrict__ sx0  = &sx[sq0 * (TT + 1)];

    float h[NSEQ][UPT], c[NSEQ][UPT];
#pragma unroll
    for (int s = 0; s < NSEQ; s++)
#pragma unroll
        for (int j = 0; j < UPT; j++) { h[s][j] = 0.0f; c[s][j] = 0.0f; }

    for (int t = 0; t < TT; t++) {
        ull aif[NSEQ][UPT], ago[NSEQ][UPT];
#pragma unroll
        for (int s = 0; s < NSEQ; s++) {
            const float xv = sx0[s * (TT + 1) + t];
            const ull xt2 = pack2(xv, xv);
#pragma unroll
            for (int j = 0; j < UPT; j++) {
                aif[s][j] = ffma2(xt2, sWinIf[u0 + j], sBif[u0 + j]);
                ago[s][j] = ffma2(xt2, sWinGo[u0 + j], sBgo[u0 + j]);
            }
        }

        // k-loop in chunks of 5 (unit ownership granularity). Shuffles for the
        // whole chunk are hoisted into hk[][] to bury the ~26cyc SHFL latency
        // under the FMA stream (R2-validated schedule).
        for (int m = 0; m < 8; m++) {
            float hk[UPT][NSEQ];
#pragma unroll
            for (int kk = 0; kk < UPT; kk++)
#pragma unroll
                for (int s = 0; s < NSEQ; s++)
                    hk[kk][s] = __shfl_sync(0xffffffffu, h[s][kk], m, 8);

            const char* base = wbase + (size_t)m * (UPT * WROW * 8);
#pragma unroll
            for (int kk = 0; kk < UPT; kk++) {
                const char* row = base + kk * (WROW * 8);
                const ulonglong2 w01 = *reinterpret_cast<const ulonglong2*>(row);
                const ulonglong2 w23 = *reinterpret_cast<const ulonglong2*>(row + 16);
                const ulonglong2 wg0 = *reinterpret_cast<const ulonglong2*>(row + 32); // if4, go0
                const ulonglong2 g12 = *reinterpret_cast<const ulonglong2*>(row + 48);
                const ulonglong2 g34 = *reinterpret_cast<const ulonglong2*>(row + 64);
#pragma unroll
                for (int s = 0; s < NSEQ; s++) {
                    const ull hk2 = pack2(hk[kk][s], hk[kk][s]);
                    aif[s][0] = ffma2(hk2, w01.x, aif[s][0]);
                    aif[s][1] = ffma2(hk2, w01.y, aif[s][1]);
                    aif[s][2] = ffma2(hk2, w23.x, aif[s][2]);
                    aif[s][3] = ffma2(hk2, w23.y, aif[s][3]);
                    aif[s][4] = ffma2(hk2, wg0.x, aif[s][4]);
                    ago[s][0] = ffma2(hk2, wg0.y, ago[s][0]);
                    ago[s][1] = ffma2(hk2, g12.x, ago[s][1]);
                    ago[s][2] = ffma2(hk2, g12.y, ago[s][2]);
                    ago[s][3] = ffma2(hk2, g34.x, ago[s][3]);
                    ago[s][4] = ffma2(hk2, g34.y, ago[s][4]);
                }
            }
        }

        // activations + state update
#pragma unroll
        for (int s = 0; s < NSEQ; s++) {
#pragma unroll
            for (int j = 0; j < UPT; j++) {
                float ig, fg, gg, og;
                unpack2(aif[s][j], ig, fg);
                unpack2(ago[s][j], gg, og);
                const float iv = sigf(ig);
                const float fv = sigf(fg);
                const float gv = tanhfast(gg);
                const float ov = sigf(og);
                // mirror jax rounding: c_new = rn(rn(f*c) + rn(i*g))
                const float cn = __fadd_rn(__fmul_rn(fv, c[s][j]), __fmul_rn(iv, gv));
                c[s][j] = cn;
                h[s][j] = __fmul_rn(ov, tanhfast(cn));
            }
        }
        // warp-synchronous: next step's shuffles (full-mask) see updated h
    }

    // ---- FC head: per-lane partials, xor-reduce over the 8-lane sub group ----
    float lg[NSEQ][4];
#pragma unroll
    for (int s = 0; s < NSEQ; s++) {
#pragma unroll
        for (int cc = 0; cc < 4; cc++) {
            float p = 0.0f;
#pragma unroll
            for (int j = 0; j < UPT; j++) p = fmaf(h[s][j], sWfc[cc * HH + u0 + j], p);
            p += __shfl_xor_sync(0xffffffffu, p, 1, 8);
            p += __shfl_xor_sync(0xffffffffu, p, 2, 8);
            p += __shfl_xor_sync(0xffffffffu, p, 4, 8);
            lg[s][cc] = __fadd_rn(p, sbfc[cc]);
        }
    }

    if (sub == 0) {
#pragma unroll
        for (int s = 0; s < NSEQ; s++) {
            const int b = seq_base + sq0 + s;
            if (b < B) {
                reinterpret_cast<float4*>(out)[b] =
                    make_float4(lg[s][0], lg[s][1], lg[s][2], lg[s][3]);
                if (out_size >= 5 * B) {
                    float best = lg[s][0];
                    int   bi   = 0;
#pragma unroll
                    for (int cc = 1; cc < 4; cc++) {
                        if (lg[s][cc] > best) { best = lg[s][cc]; bi = cc; }
                    }
                    out[(size_t)4 * B + b] = (float)bi;
                }
            }
        }
    }
}

extern "C" void kernel_launch(void* const* d_in, const int* in_sizes, int n_in,
                              void* d_out, int out_size)
{
    const float* x    = (const float*)d_in[0];
    const float* W_ih = (const float*)d_in[1];
    const float* W_hh = (const float*)d_in[2];
    const float* b_ih = (const float*)d_in[3];
    const float* b_hh = (const float*)d_in[4];
    const float* W_fc = (const float*)d_in[5];
    const float* b_fc = (const float*)d_in[6];

    const int B = in_sizes[0] / TT;
    const int threads = 128;
    const int blocks  = (B + SEQ_PER_CTA - 1) / SEQ_PER_CTA;

    lstm_fused_kernel<<<blocks, threads>>>(x, W_ih, W_hh, b_ih, b_hh,
                                           W_fc, b_fc, (float*)d_out, B, out_size);
}

// round 6
// speedup vs baseline: 1.3004x; 1.0433x over previous
#include <cuda_runtime.h>
#include <cstdint>

// Problem constants: B=131072, T=40, H=40, C=4
#define TT   40
#define HH   40
#define UPT  5            // hidden units per lane (8 subs cover H=40)
#define NSEQ 4            // sequences per lane (register reuse factor for weights)
#define SEQ_PER_WARP 16   // 4 groups * NSEQ
#define SEQ_PER_CTA  64   // 4 warps

typedef unsigned long long ull;

// ---- packed fp32x2 helpers (sm_103a: FFMA2 only via PTX) ----
__device__ __forceinline__ ull ffma2(ull a, ull b, ull c) {
    ull d;
    asm("fma.rn.f32x2 %0, %1, %2, %3;" : "=l"(d) : "l"(a), "l"(b), "l"(c));
    return d;
}
__device__ __forceinline__ ull pack2(float lo, float hi) {
    ull r;
    asm("mov.b64 %0, {%1, %2};" : "=l"(r) : "f"(lo), "f"(hi));
    return r;
}
__device__ __forceinline__ void unpack2(ull v, float& lo, float& hi) {
    asm("mov.b64 {%0, %1}, %2;" : "=f"(lo), "=f"(hi) : "l"(v));
}
__device__ __forceinline__ ull pack_bits(float lo, float hi) {
    return (ull)__float_as_uint(lo) | ((ull)__float_as_uint(hi) << 32);
}

// ---- MUFU primitives ----
__device__ __forceinline__ float ex2f(float x) {
    float r; asm("ex2.approx.f32 %0, %1;" : "=f"(r) : "f"(x)); return r;
}
__device__ __forceinline__ float rcpf(float x) {
    float r; asm("rcp.approx.f32 %0, %1;" : "=f"(r) : "f"(x)); return r;
}
__device__ __forceinline__ float sigf(float x) {
    return rcpf(1.0f + ex2f(x * -1.4426950408889634f));
}
__device__ __forceinline__ float tanhfast(float x) {
    return fmaf(-2.0f, rcpf(1.0f + ex2f(x * 2.8853900817779268f)), 1.0f);
}

#define NLOG2E (-1.4426950408889634f)
#define TLOG2E ( 2.8853901817779268f)  // 2*log2(e)

// Weight row per (sub, k): 12 ull slots (96B, keeps 16B row alignment),
// slots [0..4] = (i,f) pairs, [5..9] = (g,o) pairs -> exactly 5 LDS.128 per row.
// Per-sub stride 482 ull: +2 (16B) stagger so the 8 subs' rows land on
// distinct 16B bank groups (3856 % 128 = 16) -> conflict-free wavefronts.
#define WROW 12
#define SUBSTRIDE 482

__global__ __launch_bounds__(128)
void lstm_fused_kernel(const float* __restrict__ x,
                       const float* __restrict__ W_ih,
                       const float* __restrict__ W_hh,
                       const float* __restrict__ b_ih,
                       const float* __restrict__ b_hh,
                       const float* __restrict__ W_fc,
                       const float* __restrict__ b_fc,
                       float* __restrict__ out,
                       int B, int out_size)
{
    __shared__ __align__(16) ull sW[8 * SUBSTRIDE];           // 30.8 KB
    __shared__ __align__(16) ull sBif[HH], sBgo[HH], sWinIf[HH], sWinGo[HH];
    __shared__ float sWfc[4 * HH];
    __shared__ float sbfc[4];
    __shared__ float sx[SEQ_PER_CTA * (TT + 1)];              // padded rows

    const int tid = threadIdx.x;
    const int seq_base = blockIdx.x * SEQ_PER_CTA;

    // ---- fill packed weights ----
    for (int idx = tid; idx < HH * HH; idx += blockDim.x) {
        int k = idx / HH, u = idx % HH;
        int sub = u / UPT, j = u % UPT;
        ull* row = &sW[sub * SUBSTRIDE + k * WROW];
        row[j]     = pack_bits(W_hh[u * HH + k],          W_hh[(HH + u) * HH + k]);
        row[5 + j] = pack_bits(W_hh[(2*HH + u) * HH + k], W_hh[(3*HH + u) * HH + k]);
    }
    for (int u = tid; u < HH; u += blockDim.x) {
        sBif[u]   = pack_bits(b_ih[u]        + b_hh[u],        b_ih[HH + u]   + b_hh[HH + u]);
        sBgo[u]   = pack_bits(b_ih[2*HH + u] + b_hh[2*HH + u], b_ih[3*HH + u] + b_hh[3*HH + u]);
        sWinIf[u] = pack_bits(W_ih[u],        W_ih[HH + u]);
        sWinGo[u] = pack_bits(W_ih[2*HH + u], W_ih[3*HH + u]);
    }
    for (int i = tid; i < 4 * HH; i += blockDim.x) sWfc[i] = W_fc[i];
    if (tid < 4) sbfc[tid] = b_fc[tid];

    // ---- stage x (coalesced) ----
    for (int idx = tid; idx < SEQ_PER_CTA * TT; idx += blockDim.x) {
        int sq = idx / TT, t = idx % TT;
        int gb = seq_base + sq;
        sx[sq * (TT + 1) + t] = (gb < B) ? x[(size_t)gb * TT + t] : 0.0f;
    }
    __syncthreads();

    const int lane = tid & 31;
    const int w    = tid >> 5;
    const int sub  = lane & 7;          // unit slice: [sub*5, sub*5+5)
    const int grp  = lane >> 3;         // sequence group within warp
    const int u0   = sub * UPT;
    const int sq0  = w * SEQ_PER_WARP + grp * NSEQ;

    const char* __restrict__ wbase = (const char*)&sW[sub * SUBSTRIDE];
    const float* __restrict__ sx0  = &sx[sq0 * (TT + 1)];

    float h[NSEQ][UPT], c[NSEQ][UPT];
#pragma unroll
    for (int s = 0; s < NSEQ; s++)
#pragma unroll
        for (int j = 0; j < UPT; j++) { h[s][j] = 0.0f; c[s][j] = 0.0f; }

    for (int t = 0; t < TT; t++) {
        ull aif[NSEQ][UPT], ago[NSEQ][UPT];
#pragma unroll
        for (int s = 0; s < NSEQ; s++) {
            const float xv = sx0[s * (TT + 1) + t];
            const ull xt2 = pack2(xv, xv);
#pragma unroll
            for (int j = 0; j < UPT; j++) {
                aif[s][j] = ffma2(xt2, sWinIf[u0 + j], sBif[u0 + j]);
                ago[s][j] = ffma2(xt2, sWinGo[u0 + j], sBgo[u0 + j]);
            }
        }

        // k-loop in chunks of 5 (unit ownership granularity). Shuffles for the
        // whole chunk are hoisted into hk[][] to bury the ~26cyc SHFL latency
        // under the FMA stream (R2-validated schedule).
        for (int m = 0; m < 8; m++) {
            float hk[UPT][NSEQ];
#pragma unroll
            for (int kk = 0; kk < UPT; kk++)
#pragma unroll
                for (int s = 0; s < NSEQ; s++)
                    hk[kk][s] = __shfl_sync(0xffffffffu, h[s][kk], m, 8);

            const char* base = wbase + (size_t)m * (UPT * WROW * 8);
#pragma unroll
            for (int kk = 0; kk < UPT; kk++) {
                const char* row = base + kk * (WROW * 8);
                const ulonglong2 w01 = *reinterpret_cast<const ulonglong2*>(row);
                const ulonglong2 w23 = *reinterpret_cast<const ulonglong2*>(row + 16);
                const ulonglong2 wg0 = *reinterpret_cast<const ulonglong2*>(row + 32); // if4, go0
                const ulonglong2 g12 = *reinterpret_cast<const ulonglong2*>(row + 48);
                const ulonglong2 g34 = *reinterpret_cast<const ulonglong2*>(row + 64);
#pragma unroll
                for (int s = 0; s < NSEQ; s++) {
                    const ull hk2 = pack2(hk[kk][s], hk[kk][s]);
                    aif[s][0] = ffma2(hk2, w01.x, aif[s][0]);
                    aif[s][1] = ffma2(hk2, w01.y, aif[s][1]);
                    aif[s][2] = ffma2(hk2, w23.x, aif[s][2]);
                    aif[s][3] = ffma2(hk2, w23.y, aif[s][3]);
                    aif[s][4] = ffma2(hk2, wg0.x, aif[s][4]);
                    ago[s][0] = ffma2(hk2, wg0.y, ago[s][0]);
                    ago[s][1] = ffma2(hk2, g12.x, ago[s][1]);
                    ago[s][2] = ffma2(hk2, g12.y, ago[s][2]);
                    ago[s][3] = ffma2(hk2, g34.x, ago[s][3]);
                    ago[s][4] = ffma2(hk2, g34.y, ago[s][4]);
                }
            }
        }

        // activations + state update — shared-RCP fused form (7 MUFU/unit vs 10):
        //   c_new = f*c + i*tanh(g)
        //         = [c*D1*V1 + (v-1)*D2] / (D2*D1*V1),
        //     u=e^-i, fe=e^-f, v=e^{2g}, D1=1+u, D2=1+fe, V1=v+1
        //   h_new = sig(o)*tanh(c_new) = (w-1) / ((1+e^-o)*(w+1)),  w=e^{2*c_new}
        // Range audit: |gates|<~8, c<=T=40 -> max ex2 exponent ~115 < 126;
        // max denominator product ~8e37 < fp32 max. No overflow.
#pragma unroll
        for (int s = 0; s < NSEQ; s++) {
#pragma unroll
            for (int j = 0; j < UPT; j++) {
                float ig, fg, gg, og;
                unpack2(aif[s][j], ig, fg);
                unpack2(ago[s][j], gg, og);

                const float u_  = ex2f(ig * NLOG2E);   // e^-i
                const float fe  = ex2f(fg * NLOG2E);   // e^-f
                const float v_  = ex2f(gg * TLOG2E);   // e^{2g}
                const float D1  = 1.0f + u_;
                const float D2  = 1.0f + fe;
                const float V1  = v_ + 1.0f;
                const float Vm  = v_ - 1.0f;
                const float D1V1 = D1 * V1;
                const float num  = fmaf(c[s][j], D1V1, Vm * D2);
                const float cn   = num * rcpf(D2 * D1V1);
                c[s][j] = cn;

                const float oe = ex2f(og * NLOG2E);    // e^-o
                const float w_ = ex2f(cn * TLOG2E);    // e^{2*cn}
                const float r2 = rcpf((1.0f + oe) * (w_ + 1.0f));
                h[s][j] = (w_ - 1.0f) * r2;
            }
        }
        // warp-synchronous: next step's shuffles (full-mask) see updated h
    }

    // ---- FC head: per-lane partials, xor-reduce over the 8-lane sub group ----
    float lg[NSEQ][4];
#pragma unroll
    for (int s = 0; s < NSEQ; s++) {
#pragma unroll
        for (int cc = 0; cc < 4; cc++) {
            float p = 0.0f;
#pragma unroll
            for (int j = 0; j < UPT; j++) p = fmaf(h[s][j], sWfc[cc * HH + u0 + j], p);
            p += __shfl_xor_sync(0xffffffffu, p, 1, 8);
            p += __shfl_xor_sync(0xffffffffu, p, 2, 8);
            p += __shfl_xor_sync(0xffffffffu, p, 4, 8);
            lg[s][cc] = __fadd_rn(p, sbfc[cc]);
        }
    }

    if (sub == 0) {
#pragma unroll
        for (int s = 0; s < NSEQ; s++) {
            const int b = seq_base + sq0 + s;
            if (b < B) {
                reinterpret_cast<float4*>(out)[b] =
                    make_float4(lg[s][0], lg[s][1], lg[s][2], lg[s][3]);
                if (out_size >= 5 * B) {
                    float best = lg[s][0];
                    int   bi   = 0;
#pragma unroll
                    for (int cc = 1; cc < 4; cc++) {
                        if (lg[s][cc] > best) { best = lg[s][cc]; bi = cc; }
                    }
                    out[(size_t)4 * B + b] = (float)bi;
                }
            }
        }
    }
}

extern "C" void kernel_launch(void* const* d_in, const int* in_sizes, int n_in,
                              void* d_out, int out_size)
{
    const float* x    = (const float*)d_in[0];
    const float* W_ih = (const float*)d_in[1];
    const float* W_hh = (const float*)d_in[2];
    const float* b_ih = (const float*)d_in[3];
    const float* b_hh = (const float*)d_in[4];
    const float* W_fc = (const float*)d_in[5];
    const float* b_fc = (const float*)d_in[6];

    const int B = in_sizes[0] / TT;
    const int threads = 128;
    const int blocks  = (B + SEQ_PER_CTA - 1) / SEQ_PER_CTA;

    lstm_fused_kernel<<<blocks, threads>>>(x, W_ih, W_hh, b_ih, b_hh,
                                           W_fc, b_fc, (float*)d_out, B, out_size);
}

// round 7
// speedup vs baseline: 1.3407x; 1.0310x over previous
#include <cuda_runtime.h>
#include <cstdint>

// Problem constants: B=131072, T=40, H=40, C=4
#define TT   40
#define HH   40
#define UPT  5            // hidden units per lane (8 subs cover H=40)
#define NSEQ 5            // sequences per lane (weight reuse factor)
#define SEQ_PER_WARP 20   // 4 groups * NSEQ
#define SEQ_PER_CTA  80   // 4 warps

typedef unsigned long long ull;

// ---- packed fp32x2 helpers (sm_103a: FFMA2 only via PTX) ----
__device__ __forceinline__ ull ffma2(ull a, ull b, ull c) {
    ull d;
    asm("fma.rn.f32x2 %0, %1, %2, %3;" : "=l"(d) : "l"(a), "l"(b), "l"(c));
    return d;
}
__device__ __forceinline__ ull pack2(float lo, float hi) {
    ull r;
    asm("mov.b64 %0, {%1, %2};" : "=l"(r) : "f"(lo), "f"(hi));
    return r;
}
__device__ __forceinline__ void unpack2(ull v, float& lo, float& hi) {
    asm("mov.b64 {%0, %1}, %2;" : "=f"(lo), "=f"(hi) : "l"(v));
}
__device__ __forceinline__ ull pack_bits(float lo, float hi) {
    return (ull)__float_as_uint(lo) | ((ull)__float_as_uint(hi) << 32);
}

// ---- MUFU primitives ----
__device__ __forceinline__ float ex2f(float x) {
    float r; asm("ex2.approx.f32 %0, %1;" : "=f"(r) : "f"(x)); return r;
}
__device__ __forceinline__ float rcpf(float x) {
    float r; asm("rcp.approx.f32 %0, %1;" : "=f"(r) : "f"(x)); return r;
}

#define NLOG2E (-1.4426950408889634f)
#define TLOG2E ( 2.8853901817779268f)  // 2*log2(e)

// Weight row per (sub, k): 12 ull slots (96B, keeps 16B row alignment),
// slots [0..4] = (i,f) pairs, [5..9] = (g,o) pairs -> exactly 5 LDS.128 per row.
// Per-sub stride 482 ull: +2 (16B) stagger so the 8 subs' rows land on
// distinct 16B bank groups (3856 % 128 = 16) -> conflict-free wavefronts.
#define WROW 12
#define SUBSTRIDE 482

__global__ __launch_bounds__(128)
void lstm_fused_kernel(const float* __restrict__ x,
                       const float* __restrict__ W_ih,
                       const float* __restrict__ W_hh,
                       const float* __restrict__ b_ih,
                       const float* __restrict__ b_hh,
                       const float* __restrict__ W_fc,
                       const float* __restrict__ b_fc,
                       float* __restrict__ out,
                       int B, int out_size)
{
    __shared__ __align__(16) ull sW[8 * SUBSTRIDE];           // 30.8 KB
    __shared__ __align__(16) ull sBif[HH], sBgo[HH], sWinIf[HH], sWinGo[HH];
    __shared__ float sWfc[4 * HH];
    __shared__ float sbfc[4];
    __shared__ float sx[SEQ_PER_CTA * (TT + 1)];              // padded rows

    const int tid = threadIdx.x;
    const int seq_base = blockIdx.x * SEQ_PER_CTA;

    // ---- fill packed weights ----
    for (int idx = tid; idx < HH * HH; idx += blockDim.x) {
        int k = idx / HH, u = idx % HH;
        int sub = u / UPT, j = u % UPT;
        ull* row = &sW[sub * SUBSTRIDE + k * WROW];
        row[j]     = pack_bits(W_hh[u * HH + k],          W_hh[(HH + u) * HH + k]);
        row[5 + j] = pack_bits(W_hh[(2*HH + u) * HH + k], W_hh[(3*HH + u) * HH + k]);
    }
    for (int u = tid; u < HH; u += blockDim.x) {
        sBif[u]   = pack_bits(b_ih[u]        + b_hh[u],        b_ih[HH + u]   + b_hh[HH + u]);
        sBgo[u]   = pack_bits(b_ih[2*HH + u] + b_hh[2*HH + u], b_ih[3*HH + u] + b_hh[3*HH + u]);
        sWinIf[u] = pack_bits(W_ih[u],        W_ih[HH + u]);
        sWinGo[u] = pack_bits(W_ih[2*HH + u], W_ih[3*HH + u]);
    }
    for (int i = tid; i < 4 * HH; i += blockDim.x) sWfc[i] = W_fc[i];
    if (tid < 4) sbfc[tid] = b_fc[tid];

    // ---- stage x (coalesced) ----
    for (int idx = tid; idx < SEQ_PER_CTA * TT; idx += blockDim.x) {
        int sq = idx / TT, t = idx % TT;
        int gb = seq_base + sq;
        sx[sq * (TT + 1) + t] = (gb < B) ? x[(size_t)gb * TT + t] : 0.0f;
    }
    __syncthreads();

    const int lane = tid & 31;
    const int w    = tid >> 5;
    const int sub  = lane & 7;          // unit slice: [sub*5, sub*5+5)
    const int grp  = lane >> 3;         // sequence group within warp
    const int u0   = sub * UPT;
    const int sq0  = w * SEQ_PER_WARP + grp * NSEQ;

    const char* __restrict__ wbase = (const char*)&sW[sub * SUBSTRIDE];
    const float* __restrict__ sx0  = &sx[sq0 * (TT + 1)];

    float h[NSEQ][UPT], c[NSEQ][UPT];
#pragma unroll
    for (int s = 0; s < NSEQ; s++)
#pragma unroll
        for (int j = 0; j < UPT; j++) { h[s][j] = 0.0f; c[s][j] = 0.0f; }

    for (int t = 0; t < TT; t++) {
        ull aif[NSEQ][UPT], ago[NSEQ][UPT];
#pragma unroll
        for (int s = 0; s < NSEQ; s++) {
            const float xv = sx0[s * (TT + 1) + t];
            const ull xt2 = pack2(xv, xv);
#pragma unroll
            for (int j = 0; j < UPT; j++) {
                aif[s][j] = ffma2(xt2, sWinIf[u0 + j], sBif[u0 + j]);
                ago[s][j] = ffma2(xt2, sWinGo[u0 + j], sBgo[u0 + j]);
            }
        }

        // k-loop in chunks of 5 (unit ownership granularity). Shuffles for the
        // whole chunk are hoisted into hk[][] to bury the ~26cyc SHFL latency
        // under the FMA stream (R2-validated schedule).
        for (int m = 0; m < 8; m++) {
            float hk[UPT][NSEQ];
#pragma unroll
            for (int kk = 0; kk < UPT; kk++)
#pragma unroll
                for (int s = 0; s < NSEQ; s++)
                    hk[kk][s] = __shfl_sync(0xffffffffu, h[s][kk], m, 8);

            const char* base = wbase + (size_t)m * (UPT * WROW * 8);
#pragma unroll
            for (int kk = 0; kk < UPT; kk++) {
                const char* row = base + kk * (WROW * 8);
                const ulonglong2 w01 = *reinterpret_cast<const ulonglong2*>(row);
                const ulonglong2 w23 = *reinterpret_cast<const ulonglong2*>(row + 16);
                const ulonglong2 wg0 = *reinterpret_cast<const ulonglong2*>(row + 32); // if4, go0
                const ulonglong2 g12 = *reinterpret_cast<const ulonglong2*>(row + 48);
                const ulonglong2 g34 = *reinterpret_cast<const ulonglong2*>(row + 64);
#pragma unroll
                for (int s = 0; s < NSEQ; s++) {
                    const ull hk2 = pack2(hk[kk][s], hk[kk][s]);
                    aif[s][0] = ffma2(hk2, w01.x, aif[s][0]);
                    aif[s][1] = ffma2(hk2, w01.y, aif[s][1]);
                    aif[s][2] = ffma2(hk2, w23.x, aif[s][2]);
                    aif[s][3] = ffma2(hk2, w23.y, aif[s][3]);
                    aif[s][4] = ffma2(hk2, wg0.x, aif[s][4]);
                    ago[s][0] = ffma2(hk2, wg0.y, ago[s][0]);
                    ago[s][1] = ffma2(hk2, g12.x, ago[s][1]);
                    ago[s][2] = ffma2(hk2, g12.y, ago[s][2]);
                    ago[s][3] = ffma2(hk2, g34.x, ago[s][3]);
                    ago[s][4] = ffma2(hk2, g34.y, ago[s][4]);
                }
            }
        }

        // activations + state update — shared-RCP fused form (7 MUFU/unit):
        //   c_new = [c*D1*V1 + (v-1)*D2] / (D2*D1*V1),
        //     u=e^-i, fe=e^-f, v=e^{2g}, D1=1+u, D2=1+fe, V1=v+1
        //   h_new = (w-1) / ((1+e^-o)*(w+1)),  w=e^{2*c_new}
        // Range audit: |gates|<~8, c<=T=40 -> max ex2 exponent ~115 < 126. Safe.
#pragma unroll
        for (int s = 0; s < NSEQ; s++) {
#pragma unroll
            for (int j = 0; j < UPT; j++) {
                float ig, fg, gg, og;
                unpack2(aif[s][j], ig, fg);
                unpack2(ago[s][j], gg, og);

                const float u_  = ex2f(ig * NLOG2E);   // e^-i
                const float fe  = ex2f(fg * NLOG2E);   // e^-f
                const float v_  = ex2f(gg * TLOG2E);   // e^{2g}
                const float D1  = 1.0f + u_;
                const float D2  = 1.0f + fe;
                const float V1  = v_ + 1.0f;
                const float Vm  = v_ - 1.0f;
                const float D1V1 = D1 * V1;
                const float num  = fmaf(c[s][j], D1V1, Vm * D2);
                const float cn   = num * rcpf(D2 * D1V1);
                c[s][j] = cn;

                const float oe = ex2f(og * NLOG2E);    // e^-o
                const float w_ = ex2f(cn * TLOG2E);    // e^{2*cn}
                const float r2 = rcpf((1.0f + oe) * (w_ + 1.0f));
                h[s][j] = (w_ - 1.0f) * r2;
            }
        }
        // warp-synchronous: next step's shuffles (full-mask) see updated h
    }

    // ---- FC head: per-lane partials, xor-reduce over the 8-lane sub group ----
    float lg[NSEQ][4];
#pragma unroll
    for (int s = 0; s < NSEQ; s++) {
#pragma unroll
        for (int cc = 0; cc < 4; cc++) {
            float p = 0.0f;
#pragma unroll
            for (int j = 0; j < UPT; j++) p = fmaf(h[s][j], sWfc[cc * HH + u0 + j], p);
            p += __shfl_xor_sync(0xffffffffu, p, 1, 8);
            p += __shfl_xor_sync(0xffffffffu, p, 2, 8);
            p += __shfl_xor_sync(0xffffffffu, p, 4, 8);
            lg[s][cc] = __fadd_rn(p, sbfc[cc]);
        }
    }

    if (sub == 0) {
#pragma unroll
        for (int s = 0; s < NSEQ; s++) {
            const int b = seq_base + sq0 + s;
            if (b < B) {
                reinterpret_cast<float4*>(out)[b] =
                    make_float4(lg[s][0], lg[s][1], lg[s][2], lg[s][3]);
                if (out_size >= 5 * B) {
                    float best = lg[s][0];
                    int   bi   = 0;
#pragma unroll
                    for (int cc = 1; cc < 4; cc++) {
                        if (lg[s][cc] > best) { best = lg[s][cc]; bi = cc; }
                    }
                    out[(size_t)4 * B + b] = (float)bi;
                }
            }
        }
    }
}

extern "C" void kernel_launch(void* const* d_in, const int* in_sizes, int n_in,
                              void* d_out, int out_size)
{
    const float* x    = (const float*)d_in[0];
    const float* W_ih = (const float*)d_in[1];
    const float* W_hh = (const float*)d_in[2];
    const float* b_ih = (const float*)d_in[3];
    const float* b_hh = (const float*)d_in[4];
    const float* W_fc = (const float*)d_in[5];
    const float* b_fc = (const float*)d_in[6];

    const int B = in_sizes[0] / TT;
    const int threads = 128;
    const int blocks  = (B + SEQ_PER_CTA - 1) / SEQ_PER_CTA;

    lstm_fused_kernel<<<blocks, threads>>>(x, W_ih, W_hh, b_ih, b_hh,
                                           W_fc, b_fc, (float*)d_out, B, out_size);
}